// round 16
// baseline (speedup 1.0000x reference)
#include <cuda_runtime.h>
#include <cuda_fp16.h>
#include <cstdint>

#define NN 100000
#define NE 1600000
#define NB_SCAN ((NN + 1023) / 1024)

// Static scratch (no allocations allowed)
__device__ __half g_fH[(size_t)NN * 128];   // GEMM output (edge gather payload)
__device__ __half g_hH[(size_t)NN * 128];   // edge output (next-layer GEMM input)
__device__ float  g_el[NN * 4];
__device__ float  g_er[NN * 4];
__device__ __half g_wth[16384 * 2 + 4096];  // W hi, transposed [n][k], 3 layers
__device__ __half g_wtl[16384 * 2 + 4096];  // W lo
__device__ int    g_deg[NN];
__device__ int    g_cur[NN];                // scatter cursor (separate from deg)
__device__ int    g_off[NN + 1];
__device__ int    g_esrc[NE];               // src node per CSR position
__device__ int    g_bsum[NB_SCAN];
__device__ int    g_boff[NB_SCAN];

// ===========================================================================
// CSR build: histogram -> scan -> scatter
// ===========================================================================
__global__ void hist_kernel(const int* __restrict__ dst, int* __restrict__ deg, int E) {
    int i = blockIdx.x * blockDim.x + threadIdx.x;
    if (i < E) atomicAdd(&deg[dst[i]], 1);
}

__global__ void bsum_kernel(const int* __restrict__ deg, int* __restrict__ bsum, int n) {
    __shared__ int sm[256];
    int base = blockIdx.x * 1024;
    int t = threadIdx.x;
    int s = 0;
    for (int j = 0; j < 4; j++) {
        int idx = base + t + j * 256;
        if (idx < n) s += deg[idx];
    }
    sm[t] = s;
    __syncthreads();
    for (int d = 128; d > 0; d >>= 1) {
        if (t < d) sm[t] += sm[t + d];
        __syncthreads();
    }
    if (t == 0) bsum[blockIdx.x] = sm[0];
}

__global__ void bscan_kernel(const int* __restrict__ bsum, int* __restrict__ boff,
                             int* __restrict__ off, int nb, int n) {
    __shared__ int sm[128];
    int t = threadIdx.x;
    sm[t] = (t < nb) ? bsum[t] : 0;
    __syncthreads();
    for (int d = 1; d < 128; d <<= 1) {
        int x = (t >= d) ? sm[t - d] : 0;
        __syncthreads();
        sm[t] += x;
        __syncthreads();
    }
    if (t < nb) boff[t] = (t > 0) ? sm[t - 1] : 0;
    if (t == 127) off[n] = sm[127];
}

__global__ void scan_chunk_kernel(const int* __restrict__ deg, const int* __restrict__ boff,
                                  int* __restrict__ off, int n) {
    __shared__ int sm[256];
    int base = blockIdx.x * 1024;
    int t = threadIdx.x;
    int v[4];
    int s = 0;
    for (int j = 0; j < 4; j++) {
        int idx = base + t * 4 + j;
        v[j] = (idx < n) ? deg[idx] : 0;
        s += v[j];
    }
    sm[t] = s;
    __syncthreads();
    for (int d = 1; d < 256; d <<= 1) {
        int x = (t >= d) ? sm[t - d] : 0;
        __syncthreads();
        sm[t] += x;
        __syncthreads();
    }
    int run = ((t > 0) ? sm[t - 1] : 0) + boff[blockIdx.x];
    for (int j = 0; j < 4; j++) {
        int idx = base + t * 4 + j;
        if (idx < n) off[idx] = run;
        run += v[j];
    }
}

__global__ void scatter_kernel(const int* __restrict__ src, const int* __restrict__ dst,
                               const int* __restrict__ off, int* __restrict__ cursor,
                               int* __restrict__ esrc, int E) {
    int i = blockIdx.x * blockDim.x + threadIdx.x;
    if (i >= E) return;
    int dn = dst[i];
    int pos = off[dn] + atomicAdd(&cursor[dn], 1);
    esrc[pos] = src[i];
}

// ===========================================================================
// W prep: all three W (fp32 [k][n]) -> hi/lo fp16 transposed [n][128]
// ===========================================================================
__global__ void conv_w_all_kernel(const float* __restrict__ W1, const float* __restrict__ W2,
                                  const float* __restrict__ W3, __half* __restrict__ hi,
                                  __half* __restrict__ lo) {
    int i = blockIdx.x * blockDim.x + threadIdx.x;
    const float* W;
    int cols, base;
    if (i < 16384)      { W = W1; cols = 128; base = 0; }
    else if (i < 32768) { W = W2; cols = 128; base = 16384; }
    else if (i < 36864) { W = W3; cols = 32;  base = 32768; }
    else return;
    int j = i - base;
    int k = j / cols, n = j % cols;
    float w = W[j];
    __half h = __float2half_rn(w);
    hi[base + n * 128 + k] = h;
    lo[base + n * 128 + k] = __float2half_rn(w - __half2float(h));
}

// ===========================================================================
// Tensor-core GEMM (mma.sync m16n8k16, fp16 in / fp32 acc) + attn epilogue.
// A may be fp32 (layer 1: converted during smem fill) or fp16.
// ===========================================================================
__device__ __forceinline__ void mma16816(float* c, const uint32_t* a, uint32_t b0, uint32_t b1) {
    asm volatile(
        "mma.sync.aligned.m16n8k16.row.col.f32.f16.f16.f32 "
        "{%0,%1,%2,%3}, {%4,%5,%6,%7}, {%8,%9}, {%0,%1,%2,%3};"
        : "+f"(c[0]), "+f"(c[1]), "+f"(c[2]), "+f"(c[3])
        : "r"(a[0]), "r"(a[1]), "r"(a[2]), "r"(a[3]), "r"(b0), "r"(b1));
}

template <int COLS, typename AT>
__global__ __launch_bounds__(256) void gemm_mma_kernel(
    const AT* __restrict__ A, const __half* __restrict__ Wth,
    const __half* __restrict__ Wtl, const float* __restrict__ al,
    const float* __restrict__ ar, __half* __restrict__ F,
    float* __restrict__ el, float* __restrict__ er, int nrows) {
    constexpr int MW  = (COLS == 128) ? 4 : 8;
    constexpr int WM  = (COLS == 128) ? 2 : 1;
    constexpr int WN  = (COLS == 128) ? 8 : 4;
    constexpr int NHL = (COLS == 128) ? 2 : 1;
    constexpr int HT  = COLS / 32;
    constexpr int ST  = 136;
    constexpr bool A_IS_HALF = (sizeof(AT) == 2);

    extern __shared__ __half smh[];
    __half* As = smh;                 // [128][ST]
    __half* Wh = smh + 128 * ST;      // [COLS][ST]
    __half* Wl = Wh + COLS * ST;      // [COLS][ST]

    const int tid  = threadIdx.x;
    const int wid  = tid >> 5;
    const int lane = tid & 31;
    const int row0 = blockIdx.x * 128;

    for (int i = tid; i < 128 * 16; i += 256) {
        int r = i >> 4, q = i & 15;
        uint4 v = make_uint4(0, 0, 0, 0);
        if (row0 + r < nrows) {
            if (A_IS_HALF) {
                v = ((const uint4*)(A + (size_t)(row0 + r) * 128))[q];
            } else {
                const float4* p = (const float4*)(A + (size_t)(row0 + r) * 128) + q * 2;
                float4 f0 = p[0], f1 = p[1];
                __half2 h0 = __floats2half2_rn(f0.x, f0.y);
                __half2 h1 = __floats2half2_rn(f0.z, f0.w);
                __half2 h2 = __floats2half2_rn(f1.x, f1.y);
                __half2 h3 = __floats2half2_rn(f1.z, f1.w);
                v.x = *(uint32_t*)&h0; v.y = *(uint32_t*)&h1;
                v.z = *(uint32_t*)&h2; v.w = *(uint32_t*)&h3;
            }
        }
        ((uint4*)(As + r * ST))[q] = v;
    }
    for (int i = tid; i < COLS * 16; i += 256) {
        int r = i >> 4, q = i & 15;
        ((uint4*)(Wh + r * ST))[q] = ((const uint4*)(Wth + r * 128))[q];
        ((uint4*)(Wl + r * ST))[q] = ((const uint4*)(Wtl + r * 128))[q];
    }
    __syncthreads();

    const int m_warp = wid % MW, n_warp = wid / MW;
    const int wm = m_warp * WM * 16, wn = n_warp * WN * 8;
    const int qr = lane >> 2, qc = (lane & 3) * 2;

    float acc[WM][WN][4] = {};

#pragma unroll
    for (int kk = 0; kk < 8; kk++) {
        const int k0 = kk * 16 + qc;
        uint32_t a[WM][4];
#pragma unroll
        for (int im = 0; im < WM; im++) {
            const __half* p = As + (wm + im * 16 + qr) * ST;
            a[im][0] = *(const uint32_t*)(p + k0);
            a[im][1] = *(const uint32_t*)(p + 8 * ST + k0);
            a[im][2] = *(const uint32_t*)(p + k0 + 8);
            a[im][3] = *(const uint32_t*)(p + 8 * ST + k0 + 8);
        }
#pragma unroll
        for (int jn = 0; jn < WN; jn++) {
            const __half* ph = Wh + (wn + jn * 8 + qr) * ST;
            const __half* pl = Wl + (wn + jn * 8 + qr) * ST;
            uint32_t bh0 = *(const uint32_t*)(ph + k0);
            uint32_t bh1 = *(const uint32_t*)(ph + k0 + 8);
            uint32_t bl0 = *(const uint32_t*)(pl + k0);
            uint32_t bl1 = *(const uint32_t*)(pl + k0 + 8);
#pragma unroll
            for (int im = 0; im < WM; im++) {
                mma16816(acc[im][jn], a[im], bh0, bh1);
                mma16816(acc[im][jn], a[im], bl0, bl1);
            }
        }
    }

    float elp[WM][2][NHL] = {};
    float erp[WM][2][NHL] = {};
#pragma unroll
    for (int jn = 0; jn < WN; jn++) {
        int c = wn + jn * 8 + qc;
        float2 alv = *(const float2*)(al + c);
        float2 arv = *(const float2*)(ar + c);
        int hl = jn >> 2;
#pragma unroll
        for (int im = 0; im < WM; im++) {
            float* a4 = acc[im][jn];
            elp[im][0][hl] += a4[0] * alv.x + a4[1] * alv.y;
            erp[im][0][hl] += a4[0] * arv.x + a4[1] * arv.y;
            elp[im][1][hl] += a4[2] * alv.x + a4[3] * alv.y;
            erp[im][1][hl] += a4[2] * arv.x + a4[3] * arv.y;
            int r = row0 + wm + im * 16 + qr;
            if (r < nrows) {
                __half2 h = __floats2half2_rn(a4[0], a4[1]);
                *(__half2*)(F + (size_t)r * COLS + c) = h;
            }
            if (r + 8 < nrows) {
                __half2 h = __floats2half2_rn(a4[2], a4[3]);
                *(__half2*)(F + (size_t)(r + 8) * COLS + c) = h;
            }
        }
    }

#pragma unroll
    for (int im = 0; im < WM; im++)
#pragma unroll
        for (int rr = 0; rr < 2; rr++)
#pragma unroll
            for (int hl = 0; hl < NHL; hl++) {
                float v = elp[im][rr][hl];
                v += __shfl_xor_sync(0xffffffffu, v, 1);
                v += __shfl_xor_sync(0xffffffffu, v, 2);
                elp[im][rr][hl] = v;
                float u = erp[im][rr][hl];
                u += __shfl_xor_sync(0xffffffffu, u, 1);
                u += __shfl_xor_sync(0xffffffffu, u, 2);
                erp[im][rr][hl] = u;
            }
    if ((lane & 3) == 0) {
#pragma unroll
        for (int im = 0; im < WM; im++)
#pragma unroll
            for (int rr = 0; rr < 2; rr++) {
                int r = row0 + wm + im * 16 + qr + rr * 8;
                if (r < nrows) {
#pragma unroll
                    for (int hl = 0; hl < NHL; hl++) {
                        int hg = n_warp * NHL + hl;
                        el[r * HT + hg] = elp[im][rr][hl];
                        er[r * HT + hg] = erp[im][rr][hl];
                    }
                }
            }
    }
}

// ===========================================================================
// CSR aggregation, fused scores. One warp per node, 16 lanes per edge,
// 2 edges per iteration (sub = lane>>4 picks the edge, li = lane&15 owns
// 8 output columns via one LDG.128). w identical across the 4 lanes of a
// head group -> per-head sl needs only the final shfl_xor(16) combine.
// (segment-max shift dropped: alpha = w/s invariant; scores O(1))
// ===========================================================================
template <bool ELU>
__global__ void edge4_agg_kernel(const __half* __restrict__ F, const float* __restrict__ el,
                                 const float* __restrict__ er, const int* __restrict__ off,
                                 const int* __restrict__ esrc, const float* __restrict__ b,
                                 __half* __restrict__ outh, int n) {
    int warp = (blockIdx.x * blockDim.x + threadIdx.x) >> 5;
    int lane = threadIdx.x & 31;
    if (warp >= n) return;
    const int node = warp;
    const int sub = lane >> 4;      // which edge of the pair
    const int li  = lane & 15;      // 16B column chunk
    const int h   = li >> 2;        // head of my 8 columns

    const float erh = __ldg(er + node * 4 + h);
    const int start = off[node], end = off[node + 1];
    float acc[8] = {};
    float sl = 0.f;

#pragma unroll 2
    for (int e = start; e < end; e += 2) {
        int ee = e + sub;
        bool valid = (ee < end);
        int sn = __ldg(esrc + (valid ? ee : e));
        float v = __ldg(el + sn * 4 + h) + erh;
        v = v > 0.f ? v : 0.2f * v;
        float w = valid ? __expf(v) : 0.f;
        sl += w;
        uint4 p = *(const uint4*)(F + (size_t)sn * 128 + li * 8);
        float2 f0 = __half22float2(*(__half2*)&p.x);
        float2 f1 = __half22float2(*(__half2*)&p.y);
        float2 f2 = __half22float2(*(__half2*)&p.z);
        float2 f3 = __half22float2(*(__half2*)&p.w);
        acc[0] = fmaf(w, f0.x, acc[0]); acc[1] = fmaf(w, f0.y, acc[1]);
        acc[2] = fmaf(w, f1.x, acc[2]); acc[3] = fmaf(w, f1.y, acc[3]);
        acc[4] = fmaf(w, f2.x, acc[4]); acc[5] = fmaf(w, f2.y, acc[5]);
        acc[6] = fmaf(w, f3.x, acc[6]); acc[7] = fmaf(w, f3.y, acc[7]);
    }

#pragma unroll
    for (int j = 0; j < 8; j++) acc[j] += __shfl_xor_sync(0xffffffffu, acc[j], 16);
    sl += __shfl_xor_sync(0xffffffffu, sl, 16);

    if (lane < 16) {
        float inv = 1.f / fmaxf(sl, 1e-9f);
        int c = li * 8;
        float o[8];
#pragma unroll
        for (int j = 0; j < 8; j++) {
            o[j] = acc[j] * inv + b[c + j];
            if (ELU) o[j] = o[j] > 0.f ? o[j] : expm1f(o[j]);
        }
        __half2 h0 = __floats2half2_rn(o[0], o[1]);
        __half2 h1 = __floats2half2_rn(o[2], o[3]);
        __half2 h2 = __floats2half2_rn(o[4], o[5]);
        __half2 h3 = __floats2half2_rn(o[6], o[7]);
        uint4 u;
        u.x = *(uint32_t*)&h0; u.y = *(uint32_t*)&h1;
        u.z = *(uint32_t*)&h2; u.w = *(uint32_t*)&h3;
        *(uint4*)(outh + (size_t)node * 128 + c) = u;
    }
}

// H=1 (layer 3): 2 edges per iteration, 16 lanes each (2 cols via half2);
// combine with shfl_xor(16) at the end. fp32 output (final layer).
__global__ void edge1_agg_kernel(const __half* __restrict__ F, const float* __restrict__ el,
                                 const float* __restrict__ er, const int* __restrict__ off,
                                 const int* __restrict__ esrc, const float* __restrict__ b,
                                 float* __restrict__ out, int n) {
    int warp = (blockIdx.x * blockDim.x + threadIdx.x) >> 5;
    int lane = threadIdx.x & 31;
    if (warp >= n) return;
    const int node = warp;
    const int sub = lane >> 4;
    const int li  = lane & 15;

    const float erh = __ldg(er + node);
    const int start = off[node], end = off[node + 1];
    float acc0 = 0.f, acc1 = 0.f, sl = 0.f;

#pragma unroll 2
    for (int e = start; e < end; e += 2) {
        int ee = e + sub;
        bool valid = (ee < end);
        int sn = __ldg(esrc + (valid ? ee : e));
        float v = __ldg(el + sn) + erh;
        v = v > 0.f ? v : 0.2f * v;
        float w = valid ? __expf(v) : 0.f;
        sl += w;
        uint32_t p = *(const uint32_t*)(F + (size_t)sn * 32 + li * 2);
        float2 f = __half22float2(*(__half2*)&p);
        acc0 = fmaf(w, f.x, acc0);
        acc1 = fmaf(w, f.y, acc1);
    }

    acc0 += __shfl_xor_sync(0xffffffffu, acc0, 16);
    acc1 += __shfl_xor_sync(0xffffffffu, acc1, 16);
    sl   += __shfl_xor_sync(0xffffffffu, sl, 16);

    if (lane < 16) {
        float inv = 1.f / fmaxf(sl, 1e-9f);
        float2 o;
        o.x = acc0 * inv + b[li * 2];
        o.y = acc1 * inv + b[li * 2 + 1];
        *(float2*)(out + (size_t)node * 32 + li * 2) = o;
    }
}

// ===========================================================================
extern "C" void kernel_launch(void* const* d_in, const int* in_sizes, int n_in,
                              void* d_out, int out_size) {
    const float* x   = (const float*)d_in[0];
    const int*   src = (const int*)d_in[1];
    const int*   dst = (const int*)d_in[2];
    const float* W1  = (const float*)d_in[3];
    const float* al1 = (const float*)d_in[4];
    const float* ar1 = (const float*)d_in[5];
    const float* b1  = (const float*)d_in[6];
    const float* W2  = (const float*)d_in[7];
    const float* al2 = (const float*)d_in[8];
    const float* ar2 = (const float*)d_in[9];
    const float* b2  = (const float*)d_in[10];
    const float* W3  = (const float*)d_in[11];
    const float* al3 = (const float*)d_in[12];
    const float* ar3 = (const float*)d_in[13];
    const float* b3  = (const float*)d_in[14];
    float* out = (float*)d_out;

    const int N = in_sizes[0] / 128;
    const int E = in_sizes[1];

    __half *fH, *hH, *wth, *wtl;
    float *el, *er;
    int *deg, *cur, *off, *esrc, *bsum, *boff;
    cudaGetSymbolAddress((void**)&fH, g_fH);
    cudaGetSymbolAddress((void**)&hH, g_hH);
    cudaGetSymbolAddress((void**)&wth, g_wth);
    cudaGetSymbolAddress((void**)&wtl, g_wtl);
    cudaGetSymbolAddress((void**)&el, g_el);
    cudaGetSymbolAddress((void**)&er, g_er);
    cudaGetSymbolAddress((void**)&deg, g_deg);
    cudaGetSymbolAddress((void**)&cur, g_cur);
    cudaGetSymbolAddress((void**)&off, g_off);
    cudaGetSymbolAddress((void**)&esrc, g_esrc);
    cudaGetSymbolAddress((void**)&bsum, g_bsum);
    cudaGetSymbolAddress((void**)&boff, g_boff);

    const int SM128 = (128 + 2 * 128) * 136 * 2;
    const int SM32  = (128 + 2 * 32)  * 136 * 2;
    cudaFuncSetAttribute((const void*)gemm_mma_kernel<128, float>,
                         cudaFuncAttributeMaxDynamicSharedMemorySize, SM128);
    cudaFuncSetAttribute((const void*)gemm_mma_kernel<128, __half>,
                         cudaFuncAttributeMaxDynamicSharedMemorySize, SM128);
    cudaFuncSetAttribute((const void*)gemm_mma_kernel<32, __half>,
                         cudaFuncAttributeMaxDynamicSharedMemorySize, SM32);

    const int gemm_blocks = (N + 127) / 128;
    const int eblk = (E + 255) / 256;
    const int nb   = (N + 1023) / 1024;
    const int edge_blocks = (N * 32 + 255) / 256;

    // ---------------- prep with fork/join overlap ----------------
    // CSR build chain (stream s2) runs concurrently with W conversion +
    // layer-1 GEMM (main stream). Streams/events are host-side objects
    // (no device memory); intentionally leaked.
    cudaStream_t s2;
    cudaStreamCreateWithFlags(&s2, cudaStreamNonBlocking);
    cudaEvent_t evFork, evJoin;
    cudaEventCreateWithFlags(&evFork, cudaEventDisableTiming);
    cudaEventCreateWithFlags(&evJoin, cudaEventDisableTiming);

    cudaEventRecord(evFork, 0);
    cudaStreamWaitEvent(s2, evFork, 0);

    // --- CSR chain on s2 ---
    cudaMemsetAsync(deg, 0, (size_t)N * sizeof(int), s2);
    cudaMemsetAsync(cur, 0, (size_t)N * sizeof(int), s2);
    hist_kernel<<<eblk, 256, 0, s2>>>(dst, deg, E);
    bsum_kernel<<<nb, 256, 0, s2>>>(deg, bsum, N);
    bscan_kernel<<<1, 128, 0, s2>>>(bsum, boff, off, nb, N);
    scan_chunk_kernel<<<nb, 256, 0, s2>>>(deg, boff, off, N);
    scatter_kernel<<<eblk, 256, 0, s2>>>(src, dst, off, cur, esrc, E);
    cudaEventRecord(evJoin, s2);

    // --- main stream: W conversion + layer-1 GEMM (reads fp32 x directly) ---
    conv_w_all_kernel<<<144, 256>>>(W1, W2, W3, wth, wtl);
    gemm_mma_kernel<128, float><<<gemm_blocks, 256, SM128>>>(
        x, wth, wtl, al1, ar1, fH, el, er, N);

    cudaStreamWaitEvent(0, evJoin, 0);

    // ---------------- Layer 1 ----------------
    edge4_agg_kernel<true><<<edge_blocks, 256>>>(fH, el, er, off, esrc, b1, hH, N);

    // ---------------- Layer 2 ----------------
    gemm_mma_kernel<128, __half><<<gemm_blocks, 256, SM128>>>(
        hH, wth + 16384, wtl + 16384, al2, ar2, fH, el, er, N);
    edge4_agg_kernel<true><<<edge_blocks, 256>>>(fH, el, er, off, esrc, b2, hH, N);

    // ---------------- Layer 3 ----------------
    gemm_mma_kernel<32, __half><<<gemm_blocks, 256, SM32>>>(
        hH, wth + 32768, wtl + 32768, al3, ar3, fH, el, er, N);
    edge1_agg_kernel<<<edge_blocks, 256>>>(fH, el, er, off, esrc, b3, out, N);
}

// round 17
// speedup vs baseline: 1.0505x; 1.0505x over previous
#include <cuda_runtime.h>
#include <cuda_fp16.h>
#include <cstdint>

#define NN 100000
#define NE 1600000
#define NB_SCAN ((NN + 1023) / 1024)

// Static scratch (no allocations allowed)
__device__ __half g_fH[(size_t)NN * 128];   // GEMM output (edge gather payload)
__device__ __half g_hH[(size_t)NN * 128];   // edge output (next-layer GEMM input)
__device__ float  g_el[NN * 4];
__device__ float  g_er[NN * 4];
__device__ __half g_wth[16384 * 2 + 4096];  // W hi, transposed [n][k], 3 layers
__device__ __half g_wtl[16384 * 2 + 4096];  // W lo
__device__ int    g_deg[NN];
__device__ int    g_cur[NN];                // scatter cursor (separate from deg)
__device__ int    g_off[NN + 1];
__device__ int    g_esrc[NE];               // src node per CSR position
__device__ int    g_bsum[NB_SCAN];
__device__ int    g_boff[NB_SCAN];

// ===========================================================================
// CSR build: histogram -> scan -> scatter
// ===========================================================================
__global__ void hist_kernel(const int* __restrict__ dst, int* __restrict__ deg, int E) {
    int i = blockIdx.x * blockDim.x + threadIdx.x;
    if (i < E) atomicAdd(&deg[dst[i]], 1);
}

__global__ void bsum_kernel(const int* __restrict__ deg, int* __restrict__ bsum, int n) {
    __shared__ int sm[256];
    int base = blockIdx.x * 1024;
    int t = threadIdx.x;
    int s = 0;
    for (int j = 0; j < 4; j++) {
        int idx = base + t + j * 256;
        if (idx < n) s += deg[idx];
    }
    sm[t] = s;
    __syncthreads();
    for (int d = 128; d > 0; d >>= 1) {
        if (t < d) sm[t] += sm[t + d];
        __syncthreads();
    }
    if (t == 0) bsum[blockIdx.x] = sm[0];
}

__global__ void bscan_kernel(const int* __restrict__ bsum, int* __restrict__ boff,
                             int* __restrict__ off, int nb, int n) {
    __shared__ int sm[128];
    int t = threadIdx.x;
    sm[t] = (t < nb) ? bsum[t] : 0;
    __syncthreads();
    for (int d = 1; d < 128; d <<= 1) {
        int x = (t >= d) ? sm[t - d] : 0;
        __syncthreads();
        sm[t] += x;
        __syncthreads();
    }
    if (t < nb) boff[t] = (t > 0) ? sm[t - 1] : 0;
    if (t == 127) off[n] = sm[127];
}

__global__ void scan_chunk_kernel(const int* __restrict__ deg, const int* __restrict__ boff,
                                  int* __restrict__ off, int n) {
    __shared__ int sm[256];
    int base = blockIdx.x * 1024;
    int t = threadIdx.x;
    int v[4];
    int s = 0;
    for (int j = 0; j < 4; j++) {
        int idx = base + t * 4 + j;
        v[j] = (idx < n) ? deg[idx] : 0;
        s += v[j];
    }
    sm[t] = s;
    __syncthreads();
    for (int d = 1; d < 256; d <<= 1) {
        int x = (t >= d) ? sm[t - d] : 0;
        __syncthreads();
        sm[t] += x;
        __syncthreads();
    }
    int run = ((t > 0) ? sm[t - 1] : 0) + boff[blockIdx.x];
    for (int j = 0; j < 4; j++) {
        int idx = base + t * 4 + j;
        if (idx < n) off[idx] = run;
        run += v[j];
    }
}

__global__ void scatter_kernel(const int* __restrict__ src, const int* __restrict__ dst,
                               const int* __restrict__ off, int* __restrict__ cursor,
                               int* __restrict__ esrc, int E) {
    int i = blockIdx.x * blockDim.x + threadIdx.x;
    if (i >= E) return;
    int dn = dst[i];
    int pos = off[dn] + atomicAdd(&cursor[dn], 1);
    esrc[pos] = src[i];
}

// ===========================================================================
// W prep: all three W (fp32 [k][n]) -> hi/lo fp16 transposed [n][128]
// ===========================================================================
__global__ void conv_w_all_kernel(const float* __restrict__ W1, const float* __restrict__ W2,
                                  const float* __restrict__ W3, __half* __restrict__ hi,
                                  __half* __restrict__ lo) {
    int i = blockIdx.x * blockDim.x + threadIdx.x;
    const float* W;
    int cols, base;
    if (i < 16384)      { W = W1; cols = 128; base = 0; }
    else if (i < 32768) { W = W2; cols = 128; base = 16384; }
    else if (i < 36864) { W = W3; cols = 32;  base = 32768; }
    else return;
    int j = i - base;
    int k = j / cols, n = j % cols;
    float w = W[j];
    __half h = __float2half_rn(w);
    hi[base + n * 128 + k] = h;
    lo[base + n * 128 + k] = __float2half_rn(w - __half2float(h));
}

// ===========================================================================
// Tensor-core GEMM (mma.sync m16n8k16, fp16 in / fp32 acc) + attn epilogue.
// A may be fp32 (layer 1: converted during smem fill) or fp16.
// ===========================================================================
__device__ __forceinline__ void mma16816(float* c, const uint32_t* a, uint32_t b0, uint32_t b1) {
    asm volatile(
        "mma.sync.aligned.m16n8k16.row.col.f32.f16.f16.f32 "
        "{%0,%1,%2,%3}, {%4,%5,%6,%7}, {%8,%9}, {%0,%1,%2,%3};"
        : "+f"(c[0]), "+f"(c[1]), "+f"(c[2]), "+f"(c[3])
        : "r"(a[0]), "r"(a[1]), "r"(a[2]), "r"(a[3]), "r"(b0), "r"(b1));
}

template <int COLS, typename AT>
__global__ __launch_bounds__(256) void gemm_mma_kernel(
    const AT* __restrict__ A, const __half* __restrict__ Wth,
    const __half* __restrict__ Wtl, const float* __restrict__ al,
    const float* __restrict__ ar, __half* __restrict__ F,
    float* __restrict__ el, float* __restrict__ er, int nrows) {
    constexpr int MW  = (COLS == 128) ? 4 : 8;
    constexpr int WM  = (COLS == 128) ? 2 : 1;
    constexpr int WN  = (COLS == 128) ? 8 : 4;
    constexpr int NHL = (COLS == 128) ? 2 : 1;
    constexpr int HT  = COLS / 32;
    constexpr int ST  = 136;
    constexpr bool A_IS_HALF = (sizeof(AT) == 2);

    extern __shared__ __half smh[];
    __half* As = smh;                 // [128][ST]
    __half* Wh = smh + 128 * ST;      // [COLS][ST]
    __half* Wl = Wh + COLS * ST;      // [COLS][ST]

    const int tid  = threadIdx.x;
    const int wid  = tid >> 5;
    const int lane = tid & 31;
    const int row0 = blockIdx.x * 128;

    for (int i = tid; i < 128 * 16; i += 256) {
        int r = i >> 4, q = i & 15;
        uint4 v = make_uint4(0, 0, 0, 0);
        if (row0 + r < nrows) {
            if (A_IS_HALF) {
                v = ((const uint4*)(A + (size_t)(row0 + r) * 128))[q];
            } else {
                const float4* p = (const float4*)(A + (size_t)(row0 + r) * 128) + q * 2;
                float4 f0 = p[0], f1 = p[1];
                __half2 h0 = __floats2half2_rn(f0.x, f0.y);
                __half2 h1 = __floats2half2_rn(f0.z, f0.w);
                __half2 h2 = __floats2half2_rn(f1.x, f1.y);
                __half2 h3 = __floats2half2_rn(f1.z, f1.w);
                v.x = *(uint32_t*)&h0; v.y = *(uint32_t*)&h1;
                v.z = *(uint32_t*)&h2; v.w = *(uint32_t*)&h3;
            }
        }
        ((uint4*)(As + r * ST))[q] = v;
    }
    for (int i = tid; i < COLS * 16; i += 256) {
        int r = i >> 4, q = i & 15;
        ((uint4*)(Wh + r * ST))[q] = ((const uint4*)(Wth + r * 128))[q];
        ((uint4*)(Wl + r * ST))[q] = ((const uint4*)(Wtl + r * 128))[q];
    }
    __syncthreads();

    const int m_warp = wid % MW, n_warp = wid / MW;
    const int wm = m_warp * WM * 16, wn = n_warp * WN * 8;
    const int qr = lane >> 2, qc = (lane & 3) * 2;

    float acc[WM][WN][4] = {};

#pragma unroll
    for (int kk = 0; kk < 8; kk++) {
        const int k0 = kk * 16 + qc;
        uint32_t a[WM][4];
#pragma unroll
        for (int im = 0; im < WM; im++) {
            const __half* p = As + (wm + im * 16 + qr) * ST;
            a[im][0] = *(const uint32_t*)(p + k0);
            a[im][1] = *(const uint32_t*)(p + 8 * ST + k0);
            a[im][2] = *(const uint32_t*)(p + k0 + 8);
            a[im][3] = *(const uint32_t*)(p + 8 * ST + k0 + 8);
        }
#pragma unroll
        for (int jn = 0; jn < WN; jn++) {
            const __half* ph = Wh + (wn + jn * 8 + qr) * ST;
            const __half* pl = Wl + (wn + jn * 8 + qr) * ST;
            uint32_t bh0 = *(const uint32_t*)(ph + k0);
            uint32_t bh1 = *(const uint32_t*)(ph + k0 + 8);
            uint32_t bl0 = *(const uint32_t*)(pl + k0);
            uint32_t bl1 = *(const uint32_t*)(pl + k0 + 8);
#pragma unroll
            for (int im = 0; im < WM; im++) {
                mma16816(acc[im][jn], a[im], bh0, bh1);
                mma16816(acc[im][jn], a[im], bl0, bl1);
            }
        }
    }

    float elp[WM][2][NHL] = {};
    float erp[WM][2][NHL] = {};
#pragma unroll
    for (int jn = 0; jn < WN; jn++) {
        int c = wn + jn * 8 + qc;
        float2 alv = *(const float2*)(al + c);
        float2 arv = *(const float2*)(ar + c);
        int hl = jn >> 2;
#pragma unroll
        for (int im = 0; im < WM; im++) {
            float* a4 = acc[im][jn];
            elp[im][0][hl] += a4[0] * alv.x + a4[1] * alv.y;
            erp[im][0][hl] += a4[0] * arv.x + a4[1] * arv.y;
            elp[im][1][hl] += a4[2] * alv.x + a4[3] * alv.y;
            erp[im][1][hl] += a4[2] * arv.x + a4[3] * arv.y;
            int r = row0 + wm + im * 16 + qr;
            if (r < nrows) {
                __half2 h = __floats2half2_rn(a4[0], a4[1]);
                *(__half2*)(F + (size_t)r * COLS + c) = h;
            }
            if (r + 8 < nrows) {
                __half2 h = __floats2half2_rn(a4[2], a4[3]);
                *(__half2*)(F + (size_t)(r + 8) * COLS + c) = h;
            }
        }
    }

#pragma unroll
    for (int im = 0; im < WM; im++)
#pragma unroll
        for (int rr = 0; rr < 2; rr++)
#pragma unroll
            for (int hl = 0; hl < NHL; hl++) {
                float v = elp[im][rr][hl];
                v += __shfl_xor_sync(0xffffffffu, v, 1);
                v += __shfl_xor_sync(0xffffffffu, v, 2);
                elp[im][rr][hl] = v;
                float u = erp[im][rr][hl];
                u += __shfl_xor_sync(0xffffffffu, u, 1);
                u += __shfl_xor_sync(0xffffffffu, u, 2);
                erp[im][rr][hl] = u;
            }
    if ((lane & 3) == 0) {
#pragma unroll
        for (int im = 0; im < WM; im++)
#pragma unroll
            for (int rr = 0; rr < 2; rr++) {
                int r = row0 + wm + im * 16 + qr + rr * 8;
                if (r < nrows) {
#pragma unroll
                    for (int hl = 0; hl < NHL; hl++) {
                        int hg = n_warp * NHL + hl;
                        el[r * HT + hg] = elp[im][rr][hl];
                        er[r * HT + hg] = erp[im][rr][hl];
                    }
                }
            }
    }
}

// ===========================================================================
// CSR aggregation, fused scores, no shuffles (R14 form — empirically best).
// One warp per node; per edge: esrc broadcast LDG (line reused across 32
// edges), el gather LDG (one 16B sector), leaky+exp in-lane, payload LDG.64,
// 4 FMA. w identical across each 8-lane head group -> sl needs no reduce.
// __launch_bounds__(256, 8) forces 64 warps/SM for latency hiding.
// (segment-max shift dropped: alpha = w/s invariant; scores O(1))
// ===========================================================================
template <bool ELU>
__global__ __launch_bounds__(256, 8)
void edge4_agg_kernel(const __half* __restrict__ F, const float* __restrict__ el,
                      const float* __restrict__ er, const int* __restrict__ off,
                      const int* __restrict__ esrc, const float* __restrict__ b,
                      __half* __restrict__ outh, int n) {
    int warp = (blockIdx.x * blockDim.x + threadIdx.x) >> 5;
    int lane = threadIdx.x & 31;
    if (warp >= n) return;
    const int node = warp;
    const int h = lane >> 3;

    const float erh = __ldg(er + node * 4 + h);
    const int start = off[node], end = off[node + 1];
    float acc0 = 0.f, acc1 = 0.f, acc2 = 0.f, acc3 = 0.f, sl = 0.f;

    auto body = [&](int e) {
        int sn = __ldg(esrc + e);                       // broadcast
        float v = __ldg(el + sn * 4 + h) + erh;         // one 16B sector
        v = v > 0.f ? v : 0.2f * v;
        float w = __expf(v);
        sl += w;
        uint2 p = *(const uint2*)(F + (size_t)sn * 128 + lane * 4);
        float2 f0 = __half22float2(*(__half2*)&p.x);
        float2 f1 = __half22float2(*(__half2*)&p.y);
        acc0 = fmaf(w, f0.x, acc0);
        acc1 = fmaf(w, f0.y, acc1);
        acc2 = fmaf(w, f1.x, acc2);
        acc3 = fmaf(w, f1.y, acc3);
    };

    int e = start;
    for (; e + 4 <= end; e += 4) {
        body(e); body(e + 1); body(e + 2); body(e + 3);
    }
    for (; e < end; e++) body(e);

    float inv = 1.f / fmaxf(sl, 1e-9f);
    int c = lane * 4;
    float4 o;
    o.x = acc0 * inv + b[c + 0];
    o.y = acc1 * inv + b[c + 1];
    o.z = acc2 * inv + b[c + 2];
    o.w = acc3 * inv + b[c + 3];
    if (ELU) {
        o.x = o.x > 0.f ? o.x : expm1f(o.x);
        o.y = o.y > 0.f ? o.y : expm1f(o.y);
        o.z = o.z > 0.f ? o.z : expm1f(o.z);
        o.w = o.w > 0.f ? o.w : expm1f(o.w);
    }
    __half2 h0 = __floats2half2_rn(o.x, o.y);
    __half2 h1 = __floats2half2_rn(o.z, o.w);
    uint2 u;
    u.x = *(uint32_t*)&h0; u.y = *(uint32_t*)&h1;
    ((uint2*)(outh + (size_t)node * 128))[lane] = u;
}

// H=1 (layer 3): 2 edges per iteration, 16 lanes each (2 cols via half2);
// combine with shfl_xor(16) at the end. fp32 output (final layer).
__global__ __launch_bounds__(256, 8)
void edge1_agg_kernel(const __half* __restrict__ F, const float* __restrict__ el,
                      const float* __restrict__ er, const int* __restrict__ off,
                      const int* __restrict__ esrc, const float* __restrict__ b,
                      float* __restrict__ out, int n) {
    int warp = (blockIdx.x * blockDim.x + threadIdx.x) >> 5;
    int lane = threadIdx.x & 31;
    if (warp >= n) return;
    const int node = warp;
    const int sub = lane >> 4;
    const int li  = lane & 15;

    const float erh = __ldg(er + node);
    const int start = off[node], end = off[node + 1];
    float acc0 = 0.f, acc1 = 0.f, sl = 0.f;

#pragma unroll 2
    for (int e = start; e < end; e += 2) {
        int ee = e + sub;
        bool valid = (ee < end);
        int sn = __ldg(esrc + (valid ? ee : e));
        float v = __ldg(el + sn) + erh;
        v = v > 0.f ? v : 0.2f * v;
        float w = valid ? __expf(v) : 0.f;
        sl += w;
        uint32_t p = *(const uint32_t*)(F + (size_t)sn * 32 + li * 2);
        float2 f = __half22float2(*(__half2*)&p);
        acc0 = fmaf(w, f.x, acc0);
        acc1 = fmaf(w, f.y, acc1);
    }

    acc0 += __shfl_xor_sync(0xffffffffu, acc0, 16);
    acc1 += __shfl_xor_sync(0xffffffffu, acc1, 16);
    sl   += __shfl_xor_sync(0xffffffffu, sl, 16);

    if (lane < 16) {
        float inv = 1.f / fmaxf(sl, 1e-9f);
        float2 o;
        o.x = acc0 * inv + b[li * 2];
        o.y = acc1 * inv + b[li * 2 + 1];
        *(float2*)(out + (size_t)node * 32 + li * 2) = o;
    }
}

// ===========================================================================
extern "C" void kernel_launch(void* const* d_in, const int* in_sizes, int n_in,
                              void* d_out, int out_size) {
    const float* x   = (const float*)d_in[0];
    const int*   src = (const int*)d_in[1];
    const int*   dst = (const int*)d_in[2];
    const float* W1  = (const float*)d_in[3];
    const float* al1 = (const float*)d_in[4];
    const float* ar1 = (const float*)d_in[5];
    const float* b1  = (const float*)d_in[6];
    const float* W2  = (const float*)d_in[7];
    const float* al2 = (const float*)d_in[8];
    const float* ar2 = (const float*)d_in[9];
    const float* b2  = (const float*)d_in[10];
    const float* W3  = (const float*)d_in[11];
    const float* al3 = (const float*)d_in[12];
    const float* ar3 = (const float*)d_in[13];
    const float* b3  = (const float*)d_in[14];
    float* out = (float*)d_out;

    const int N = in_sizes[0] / 128;
    const int E = in_sizes[1];

    __half *fH, *hH, *wth, *wtl;
    float *el, *er;
    int *deg, *cur, *off, *esrc, *bsum, *boff;
    cudaGetSymbolAddress((void**)&fH, g_fH);
    cudaGetSymbolAddress((void**)&hH, g_hH);
    cudaGetSymbolAddress((void**)&wth, g_wth);
    cudaGetSymbolAddress((void**)&wtl, g_wtl);
    cudaGetSymbolAddress((void**)&el, g_el);
    cudaGetSymbolAddress((void**)&er, g_er);
    cudaGetSymbolAddress((void**)&deg, g_deg);
    cudaGetSymbolAddress((void**)&cur, g_cur);
    cudaGetSymbolAddress((void**)&off, g_off);
    cudaGetSymbolAddress((void**)&esrc, g_esrc);
    cudaGetSymbolAddress((void**)&bsum, g_bsum);
    cudaGetSymbolAddress((void**)&boff, g_boff);

    const int SM128 = (128 + 2 * 128) * 136 * 2;
    const int SM32  = (128 + 2 * 32)  * 136 * 2;
    cudaFuncSetAttribute((const void*)gemm_mma_kernel<128, float>,
                         cudaFuncAttributeMaxDynamicSharedMemorySize, SM128);
    cudaFuncSetAttribute((const void*)gemm_mma_kernel<128, __half>,
                         cudaFuncAttributeMaxDynamicSharedMemorySize, SM128);
    cudaFuncSetAttribute((const void*)gemm_mma_kernel<32, __half>,
                         cudaFuncAttributeMaxDynamicSharedMemorySize, SM32);

    const int gemm_blocks = (N + 127) / 128;
    const int eblk = (E + 255) / 256;
    const int nb   = (N + 1023) / 1024;
    const int edge_blocks = (N * 32 + 255) / 256;

    // ---------------- prep with fork/join overlap ----------------
    // CSR build chain (stream s2) runs concurrently with W conversion +
    // layer-1 GEMM (main stream). Streams/events are host-side objects
    // (no device memory); intentionally leaked.
    cudaStream_t s2;
    cudaStreamCreateWithFlags(&s2, cudaStreamNonBlocking);
    cudaEvent_t evFork, evJoin;
    cudaEventCreateWithFlags(&evFork, cudaEventDisableTiming);
    cudaEventCreateWithFlags(&evJoin, cudaEventDisableTiming);

    cudaEventRecord(evFork, 0);
    cudaStreamWaitEvent(s2, evFork, 0);

    // --- CSR chain on s2 ---
    cudaMemsetAsync(deg, 0, (size_t)N * sizeof(int), s2);
    cudaMemsetAsync(cur, 0, (size_t)N * sizeof(int), s2);
    hist_kernel<<<eblk, 256, 0, s2>>>(dst, deg, E);
    bsum_kernel<<<nb, 256, 0, s2>>>(deg, bsum, N);
    bscan_kernel<<<1, 128, 0, s2>>>(bsum, boff, off, nb, N);
    scan_chunk_kernel<<<nb, 256, 0, s2>>>(deg, boff, off, N);
    scatter_kernel<<<eblk, 256, 0, s2>>>(src, dst, off, cur, esrc, E);
    cudaEventRecord(evJoin, s2);

    // --- main stream: W conversion + layer-1 GEMM (reads fp32 x directly) ---
    conv_w_all_kernel<<<144, 256>>>(W1, W2, W3, wth, wtl);
    gemm_mma_kernel<128, float><<<gemm_blocks, 256, SM128>>>(
        x, wth, wtl, al1, ar1, fH, el, er, N);

    cudaStreamWaitEvent(0, evJoin, 0);

    // ---------------- Layer 1 ----------------
    edge4_agg_kernel<true><<<edge_blocks, 256>>>(fH, el, er, off, esrc, b1, hH, N);

    // ---------------- Layer 2 ----------------
    gemm_mma_kernel<128, __half><<<gemm_blocks, 256, SM128>>>(
        hH, wth + 16384, wtl + 16384, al2, ar2, fH, el, er, N);
    edge4_agg_kernel<true><<<edge_blocks, 256>>>(fH, el, er, off, esrc, b2, hH, N);

    // ---------------- Layer 3 ----------------
    gemm_mma_kernel<32, __half><<<gemm_blocks, 256, SM32>>>(
        hH, wth + 32768, wtl + 32768, al3, ar3, fH, el, er, N);
    edge1_agg_kernel<<<edge_blocks, 256>>>(fH, el, er, off, esrc, b3, out, N);
}